// round 15
// baseline (speedup 1.0000x reference)
#include <cuda_runtime.h>
#include <math.h>

#ifndef M_PI
#define M_PI 3.14159265358979323846
#endif

// ---------------- dims ----------------
#define EDIM 128
#define HID 256
#define CINCH 26
#define COUTCH 26
#define NLAT 361
#define NLONF 720
#define TSM 90
#define NLONS 180
#define LMAXD 90
#define MMAXD 91
#define M2 182            // 2*MMAX (re,im rows)
#define PFULL (NLAT*NLONF)   // 259920
#define PSMALL (TSM*NLONS)   // 16200
#define NBLK 4

typedef unsigned long long u64;

// ---------------- device scratch ----------------
__device__ float g_Pw_full[LMAXD*MMAXD*NLAT];
__device__ float g_PinvD_full[M2*NLAT*LMAXD];     // duplicated: [182][t][l]
__device__ float g_Pw_small[LMAXD*MMAXD*TSM];
__device__ float g_PinvD_small[M2*TSM*LMAXD];
__device__ float g_Tf_full[M2*NLONF];
__device__ float g_Ti_full[NLONF*M2];
__device__ float g_Tf_small[M2*NLONS];
__device__ float g_Ti_small[NLONS*M2];
__device__ float g_Wbig[(long long)NBLK*LMAXD*65536];
__device__ float g_wT_enc0[CINCH*EDIM];
__device__ float g_wT_enc1[EDIM*EDIM];
__device__ float g_wT_mlp1[NBLK*EDIM*HID];
__device__ float g_wT_mlp2[NBLK*HID*EDIM];
__device__ float g_wT_skip[NBLK*EDIM*EDIM];
__device__ float g_wT_dec0[(EDIM+CINCH)*EDIM];
__device__ float g_wT_dec1[EDIM*COUTCH];
__device__ float g_xin[PFULL*CINCH];
__device__ float g_bufA[PFULL*EDIM];
__device__ float g_bufBC[2ll*PFULL*EDIM];         // bufB = first half, bufC = second half
__device__ float g_bufD[PFULL*EDIM];
__device__ float g_bufE[PSMALL*EDIM];
__device__ float g_bufH[PFULL*HID];
__device__ float g_G1[NLAT*M2*EDIM];              // fwd-rFFT output [t][m2][128]
__device__ float g_Gc[NLAT*M2*256];               // combined synthesis out [t][182][256]
__device__ float g_cAB[LMAXD*M2*256];             // [l][182][256]: z<91 spec, z>=91 res(skip)
__device__ float g_cRaw[LMAXD*MMAXD*256];         // raw analysis coeffs [l][91][256]
__device__ float g_stats8[8*2*EDIM];              // per (block,norm) raw sums; zeroed each replay
// legendre recurrence tables
__device__ double2 g_ab[LMAXD*MMAXD];
__device__ double g_pdiag[MMAXD];
__device__ double g_em[MMAXD];

__device__ __forceinline__ float gelu_f(float x){
    return 0.5f*x*(1.0f+erff(x*0.7071067811865475f));
}

// ---------------- setup kernels ----------------
__global__ void legtab_k(){
    int gid = blockIdx.x*blockDim.x + threadIdx.x;
    if (gid < LMAXD*MMAXD){
        int m = gid % MMAXD, l = gid / MMAXD;
        double2 ab = {0.0, 0.0};
        if (m < LMAXD && l >= m+2){
            double dl = (double)l, dm = (double)m;
            ab.x = sqrt((4.0*dl*dl-1.0)/(dl*dl-dm*dm));
            ab.y = sqrt(((dl-1.0)*(dl-1.0)-dm*dm)/(4.0*(dl-1.0)*(dl-1.0)-1.0));
        }
        g_ab[gid] = ab;
    }
    if (gid < MMAXD){
        double p = 1.0;
        for (int mm = 1; mm <= gid; mm++)
            p *= sqrt((2.0*mm+1.0)/(2.0*mm));
        g_pdiag[gid] = p;
        g_em[gid] = sqrt(2.0*gid+3.0);
    }
}

__device__ __forceinline__ void legendre_body(float* __restrict__ Pw, float* __restrict__ PinvD,
                                              int T, int gid){
    int t = gid % T, m = gid / T;
    long long d0 = ((long long)m*T + t)*LMAXD;
    long long d1 = ((long long)(MMAXD+m)*T + t)*LMAXD;
    if (m >= LMAXD){
        for (int l = 0; l < LMAXD; l++){
            Pw[((long long)l*MMAXD + m)*T + t] = 0.f;
            PinvD[d0 + l] = 0.f;
            PinvD[d1 + l] = 0.f;
        }
        return;
    }
    double theta = M_PI*((double)t + 0.5)/(double)T;
    double ct = cos(theta), st = sin(theta);
    double w = (M_PI/(double)T)*st;
    double diag = sqrt(1.0/(4.0*M_PI)) * g_pdiag[m] * pow(st, (double)m);
    double em = g_em[m];
    double pl1 = 0.0, pl2 = 0.0;
    for (int l = 0; l < LMAXD; l++){
        double v;
        if (l < m) v = 0.0;
        else if (l == m) v = diag;
        else if (l == m+1) v = em*ct*diag;
        else {
            double2 ab = g_ab[l*MMAXD + m];
            v = ab.x*(ct*pl1 - ab.y*pl2);
        }
        pl2 = pl1; pl1 = v;
        Pw[((long long)l*MMAXD + m)*T + t] = (float)(v*w);
        float fv = (float)v;
        PinvD[d0 + l] = fv;
        PinvD[d1 + l] = fv;
    }
}

__global__ void legendre_both_k(float* Pwf, float* PinvDf, float* Pws, float* PinvDs){
    int gid = blockIdx.x*blockDim.x + threadIdx.x;
    const int totf = NLAT*MMAXD;
    if (gid < totf) legendre_body(Pwf, PinvDf, NLAT, gid);
    else if (gid < totf + TSM*MMAXD) legendre_body(Pws, PinvDs, TSM, gid - totf);
}

__global__ void fft_both_k(float* Tff, float* Tif, float* Tfs, float* Tis){
    int n = (blockIdx.y == 0) ? NLONF : NLONS;
    float* Tf = (blockIdx.y == 0) ? Tff : Tfs;
    float* Ti = (blockIdx.y == 0) ? Tif : Tis;
    int idx = blockIdx.x*blockDim.x + threadIdx.x;
    if (idx >= MMAXD*n) return;
    int m = idx / n, j = idx % n;
    double ang = (2.0*M_PI*(double)m*(double)j)/(double)n;
    double s, c;
    sincos(ang, &s, &c);
    double sc = 2.0*M_PI/(double)n;
    Tf[(2*m)*n + j]   = (float)(c*sc);
    Tf[(2*m+1)*n + j] = (float)(-s*sc);
    bool nyq = (2*m == n);
    double am = (m == 0 || nyq) ? 1.0 : 2.0;
    Ti[(long long)j*M2 + 2*m]   = (float)(am*c);
    Ti[(long long)j*M2 + 2*m+1] = (m == 0 || nyq) ? 0.0f : (float)(-2.0*s);
}

__global__ void wtrans_all_k(const float* w_enc0, const float* w_enc1,
                             const float* w_mlp1, const float* w_mlp2, const float* w_skip,
                             const float* w_dec0, const float* w_dec1,
                             float* wTe0, float* wTe1, float* wTm1, float* wTm2,
                             float* wTsk, float* wTd0, float* wTd1){
    int seg = blockIdx.y;
    const float* src; float* dst; int R, C;
    if (seg == 0){ src = w_enc0; dst = wTe0; R = EDIM; C = CINCH; }
    else if (seg == 1){ src = w_enc1; dst = wTe1; R = EDIM; C = EDIM; }
    else if (seg < 6){ int i = seg-2; src = w_mlp1 + (long long)i*HID*EDIM; dst = wTm1 + (long long)i*EDIM*HID; R = HID; C = EDIM; }
    else if (seg < 10){ int i = seg-6; src = w_mlp2 + (long long)i*EDIM*HID; dst = wTm2 + (long long)i*HID*EDIM; R = EDIM; C = HID; }
    else if (seg < 14){ int i = seg-10; src = w_skip + (long long)i*EDIM*EDIM; dst = wTsk + (long long)i*EDIM*EDIM; R = EDIM; C = EDIM; }
    else if (seg == 14){ src = w_dec0; dst = wTd0; R = EDIM; C = EDIM+CINCH; }
    else { src = w_dec1; dst = wTd1; R = COUTCH; C = EDIM; }
    int tot = R*C;
    for (int idx = blockIdx.x*blockDim.x + threadIdx.x; idx < tot; idx += gridDim.x*blockDim.x){
        int c = idx % C, r = idx / C;
        dst[(long long)c*R + r] = src[idx];
    }
}

__global__ void transpose_tiled_k(const float* __restrict__ in, float* __restrict__ out,
                                  int R, int C){
    __shared__ float tile[32][33];
    int c0 = blockIdx.x*32, r0 = blockIdx.y*32;
    int tx = threadIdx.x, ty = threadIdx.y;
    int r = r0 + ty, c = c0 + tx;
    if (r < R && c < C) tile[ty][tx] = in[(long long)r*C + c];
    __syncthreads();
    int r2 = r0 + tx, c2 = c0 + ty;
    if (r2 < R && c2 < C) out[(long long)c2*R + r2] = tile[tx][ty];
}

__global__ void build_wbig2_k(const float* __restrict__ wr, const float* __restrict__ wi,
                              float* __restrict__ W){
    __shared__ float sr[64*90];
    __shared__ float si[64*90];
    int oh = blockIdx.x;
    int i  = blockIdx.y;
    int b  = blockIdx.z;
    int tid = threadIdx.x;
    for (int j = tid; j < 64*90; j += 256){
        int ol = j / 90, l = j % 90;
        int o = oh*64 + ol;
        long long src = (((long long)b*EDIM + o)*EDIM + i)*LMAXD + l;
        sr[j] = wr[src];
        si[j] = wi[src];
    }
    __syncthreads();
    for (int j = tid; j < 64*90; j += 256){
        int l = j / 64, ol = j % 64;
        int o = oh*64 + ol;
        float vr = sr[ol*90 + l], vi = si[ol*90 + l];
        float* M = W + ((long long)b*LMAXD + l)*65536;
        M[(long long)i*256 + o]             = vr;
        M[(long long)i*256 + 128 + o]       = vi;
        M[(long long)(128+i)*256 + o]       = -vi;
        M[(long long)(128+i)*256 + 128 + o] = vr;
    }
}

__global__ void zero_k(float* p, int n){
    int i = blockIdx.x*blockDim.x + threadIdx.x;
    if (i < n) p[i] = 0.0f;
}

// y = inorm(b) + c, with mu/rs computed from raw sums fstats
__global__ void inorm_add_k(const float* __restrict__ b, const float* __restrict__ c,
                            float* __restrict__ y, const float* __restrict__ fstats,
                            float invP,
                            const float* __restrict__ g, const float* __restrict__ bb,
                            long long total4){
    __shared__ float ms[2*EDIM];
    if (threadIdx.x < EDIM){
        float mu = fstats[threadIdx.x]*invP;
        float rs = rsqrtf(fstats[EDIM+threadIdx.x]*invP - mu*mu + 1e-6f);
        ms[threadIdx.x] = mu;
        ms[EDIM+threadIdx.x] = rs;
    }
    __syncthreads();
    long long i = (long long)blockIdx.x*blockDim.x + threadIdx.x;
    if (i >= total4) return;
    int ch = (int)((i & 31) << 2);
    float4 vb = ((const float4*)b)[i];
    float4 vc = ((const float4*)c)[i];
    float4 o;
    o.x = (vb.x - ms[ch  ])*ms[EDIM+ch  ]*g[ch  ] + bb[ch  ] + vc.x;
    o.y = (vb.y - ms[ch+1])*ms[EDIM+ch+1]*g[ch+1] + bb[ch+1] + vc.y;
    o.z = (vb.z - ms[ch+2])*ms[EDIM+ch+2]*g[ch+2] + bb[ch+2] + vc.z;
    o.w = (vb.w - ms[ch+3])*ms[EDIM+ch+3]*g[ch+3] + bb[ch+3] + vc.w;
    ((float4*)y)[i] = o;
}

// ---------------- generic batched GEMM (FFMA2 inner loop; hot path == R12) ----------------
// act: 0 none; 1 gelu(acc+bias) then +add; 2 gelu(acc+bias+add); 3 acc + inorm(addp)
// fstats != null: per-CTA murs table built from raw sums.
//   act != 3: A loads -> gelu((a-mu[k])*rs[k]*ng[k]+nb[k])
//   act == 3: epilogue v += inorm(addp) (channel = n)
// tri: 0 none; 1 per-batch K-clamp k_start=z%91; 2 skip CTA if m0 > z;
//      3 skip CTA if m0+TBM <= z; 4 dual out: r=z&1, z>>=1, B+=r*sB2, C+=r*sC2;
//      7 skip CTA if (m0>>1) > z (spectral-skip triangular)
// sstat: accumulate per-channel sum/sumsq of written C (requires N==128 grid.x==1)
#define BN 128
#define BKK 16

template<int TBM>
__global__ __launch_bounds__(512, 2)
void gemm_k(const float* __restrict__ A, const float* __restrict__ B,
            float* __restrict__ C,
            const float* __restrict__ bias, const float* __restrict__ addp,
            int M, int N, int K, int lda, int ldb, int ldc,
            long long sA, long long sB, long long sC, int act,
            const float* __restrict__ fstats, float invP,
            const float* __restrict__ ng, const float* __restrict__ nb,
            int tri, long long sB2, long long sC2,
            float* __restrict__ sstat){
    constexpr int MR = TBM/16;
    constexpr int ALD = (TBM == 128) ? 4 : 2;
    __shared__ float As[2][BKK][TBM+4];
    __shared__ float Bs[2][BKK][BN];
    __shared__ float ms[2*EDIM];

    long long z = blockIdx.z;
    int m0 = blockIdx.y*TBM, n0 = blockIdx.x*BN;

    int rpair = 0;
    if (tri == 4){ rpair = (int)(z & 1); z >>= 1; if (rpair) sstat = nullptr; }
    else if (tri == 2){ if (m0 > (int)z) return; }
    else if (tri == 3){ if (m0 + TBM <= (int)z) return; }
    else if (tri == 7){ if ((m0 >> 1) > (int)z) return; }

    A += z*sA; B += z*sB + (long long)rpair*sB2; C += z*sC + (long long)rpair*sC2;
    if (addp) addp += z*sC;
    if (tri == 1){
        int mm = (int)(z % MMAXD);
        A += mm;
        B += (long long)mm*ldb;
        K -= mm;
    }
    int tid = threadIdx.x;

    const bool useF = (fstats != nullptr);
    if (useF){
        if (tid < EDIM){
            float mu = fstats[tid]*invP;
            float rs = rsqrtf(fstats[EDIM+tid]*invP - mu*mu + 1e-6f);
            ms[tid] = mu;
            ms[EDIM+tid] = rs;
        }
        __syncthreads();
    }
    const bool doNA = useF && (act != 3);

    int a_m = (TBM == 128) ? (tid >> 2) : (tid >> 3);
    int a_k = (TBM == 128) ? ((tid & 3)*ALD) : ((tid & 7)*ALD);
    int b_k = tid >> 5;
    int b_n = (tid & 31) * 4;

    int ty = tid >> 5;
    int tx = tid & 31;

    bool am_ok = (m0 + a_m) < M;
    const float* Ap = A + (long long)(am_ok ? (m0 + a_m) : 0)*lda + a_k;
    const float* Bp = B + (long long)b_k*ldb + n0 + b_n;
    bool bn_ok[4];
    #pragma unroll
    for (int s = 0; s < 4; s++) bn_ok[s] = (n0 + b_n + s) < N;

    int ktiles = (K + BKK - 1)/BKK;

    u64 acc2[MR/2][4];
    #pragma unroll
    for (int rq = 0; rq < MR/2; rq++)
        #pragma unroll
        for (int c = 0; c < 4; c++)
            acc2[rq][c] = 0ull;
    float ra[ALD], rb[4];

    {
        #pragma unroll
        for (int s = 0; s < ALD; s++){
            bool ok = am_ok && (a_k+s) < K;
            float a = ok ? Ap[s] : 0.f;
            if (doNA && ok){
                int ch = a_k + s;
                a = gelu_f((a - ms[ch])*ms[EDIM+ch]*ng[ch] + nb[ch]);
            }
            As[0][a_k+s][a_m] = a;
        }
        #pragma unroll
        for (int s = 0; s < 4; s++)
            Bs[0][b_k][b_n+s] = (b_k < K && bn_ok[s]) ? Bp[s] : 0.f;
    }
    __syncthreads();
    Ap += BKK; Bp += (long long)BKK*ldb;

    int buf = 0;
    for (int it = 0; it < ktiles; it++){
        bool haveNext = (it + 1 < ktiles);
        if (haveNext){
            int kbase = (it + 1)*BKK;
            if (kbase + BKK <= K){
                #pragma unroll
                for (int s = 0; s < ALD; s++){
                    ra[s] = am_ok ? Ap[s] : 0.f;
                    if (doNA && am_ok){
                        int ch = kbase + a_k + s;
                        ra[s] = gelu_f((ra[s] - ms[ch])*ms[EDIM+ch]*ng[ch] + nb[ch]);
                    }
                }
                #pragma unroll
                for (int s = 0; s < 4; s++) rb[s] = bn_ok[s] ? Bp[s] : 0.f;
            } else {
                #pragma unroll
                for (int s = 0; s < ALD; s++){
                    bool ok = am_ok && (kbase + a_k + s) < K;
                    ra[s] = ok ? Ap[s] : 0.f;
                    if (doNA && ok){
                        int ch = kbase + a_k + s;
                        ra[s] = gelu_f((ra[s] - ms[ch])*ms[EDIM+ch]*ng[ch] + nb[ch]);
                    }
                }
                #pragma unroll
                for (int s = 0; s < 4; s++)
                    rb[s] = ((kbase + b_k) < K && bn_ok[s]) ? Bp[s] : 0.f;
            }
            Ap += BKK; Bp += (long long)BKK*ldb;
        }
        #pragma unroll
        for (int k = 0; k < BKK; k++){
            float4 b0 = *(const float4*)&Bs[buf][k][tx*4];
            u64 bb[4];
            asm("mov.b64 %0, {%1,%1};" : "=l"(bb[0]) : "r"(__float_as_uint(b0.x)));
            asm("mov.b64 %0, {%1,%1};" : "=l"(bb[1]) : "r"(__float_as_uint(b0.y)));
            asm("mov.b64 %0, {%1,%1};" : "=l"(bb[2]) : "r"(__float_as_uint(b0.z)));
            asm("mov.b64 %0, {%1,%1};" : "=l"(bb[3]) : "r"(__float_as_uint(b0.w)));
            #pragma unroll
            for (int rq = 0; rq < MR/2; rq++){
                u64 ap = *(const u64*)&As[buf][k][ty*MR + rq*2];
                #pragma unroll
                for (int c = 0; c < 4; c++)
                    asm("fma.rn.f32x2 %0, %1, %2, %0;"
                        : "+l"(acc2[rq][c]) : "l"(ap), "l"(bb[c]));
            }
        }
        if (haveNext){
            int nbuf = buf ^ 1;
            #pragma unroll
            for (int s = 0; s < ALD; s++)
                As[nbuf][a_k+s][a_m] = ra[s];
            #pragma unroll
            for (int s = 0; s < 4; s++)
                Bs[nbuf][b_k][b_n+s] = rb[s];
        }
        __syncthreads();
        buf ^= 1;
    }

    float cs[4] = {0.f,0.f,0.f,0.f};
    float cq[4] = {0.f,0.f,0.f,0.f};
    #pragma unroll
    for (int rq = 0; rq < MR/2; rq++){
        #pragma unroll
        for (int c = 0; c < 4; c++){
            unsigned lo, hi;
            asm("mov.b64 {%0,%1}, %2;" : "=r"(lo), "=r"(hi) : "l"(acc2[rq][c]));
            float v0 = __uint_as_float(lo);
            float v1 = __uint_as_float(hi);
            #pragma unroll
            for (int half = 0; half < 2; half++){
                float v = half ? v1 : v0;
                int m = m0 + ty*MR + rq*2 + half;
                int n = n0 + tx*4 + c;
                if (m >= M || n >= N) continue;
                if (bias) v += bias[n];
                if (act == 2){
                    v += addp[(long long)m*ldc + n];
                    v = gelu_f(v);
                } else if (act == 3){
                    float ad = addp[(long long)m*ldc + n];
                    v += (ad - ms[n])*ms[EDIM+n]*ng[n] + nb[n];
                } else {
                    if (act == 1) v = gelu_f(v);
                    if (addp) v += addp[(long long)m*ldc + n];
                }
                C[(long long)m*ldc + n] = v;
                if (sstat){ cs[c] += v; cq[c] += v*v; }
            }
        }
    }
    if (sstat){
        __syncthreads();
        float* rs = &As[0][0][0];
        float* rq2 = &Bs[0][0][0];
        int base = ty*128 + tx*4;
        #pragma unroll
        for (int c = 0; c < 4; c++){ rs[base+c] = cs[c]; rq2[base+c] = cq[c]; }
        __syncthreads();
        if (tid < 128){
            float s = 0.f, q = 0.f;
            #pragma unroll
            for (int t = 0; t < 16; t++){ s += rs[t*128 + tid]; q += rq2[t*128 + tid]; }
            atomicAdd(&sstat[tid], s);
            atomicAdd(&sstat[EDIM + tid], q);
        }
    }
}

// ---------------- host helpers ----------------
static void launch_gemm(const float* A, const float* B, float* C,
                        const float* bias, const float* addp,
                        int M, int N, int K, int lda, int ldb, int ldc,
                        long long sA, long long sB, long long sC, int batch, int act,
                        const float* fstats = nullptr, float invP = 0.f,
                        const float* ng = nullptr, const float* nb = nullptr,
                        int tri = 0, long long sB2 = 0, long long sC2 = 0,
                        float* sstat = nullptr){
    if (M <= 192){
        dim3 grid((N+BN-1)/BN, (M+63)/64, batch);
        gemm_k<64><<<grid, 512>>>(A, B, C, bias, addp, M, N, K, lda, ldb, ldc, sA, sB, sC, act, fstats, invP, ng, nb, tri, sB2, sC2, sstat);
    } else {
        dim3 grid((N+BN-1)/BN, (M+127)/128, batch);
        gemm_k<128><<<grid, 512>>>(A, B, C, bias, addp, M, N, K, lda, ldb, ldc, sA, sB, sC, act, fstats, invP, ng, nb, tri, sB2, sC2, sstat);
    }
}

#define SYMP(var, sym) do { void* _t = nullptr; cudaGetSymbolAddress(&_t, sym); var = (float*)_t; } while(0)

extern "C" void kernel_launch(void* const* d_in, const int* in_sizes, int n_in,
                              void* d_out, int out_size){
    const float* x_in    = (const float*)d_in[0];
    const float* w_enc0  = (const float*)d_in[1];
    const float* b_enc0  = (const float*)d_in[2];
    const float* w_enc1  = (const float*)d_in[3];
    const float* w_specr = (const float*)d_in[4];
    const float* w_speci = (const float*)d_in[5];
    const float* g0      = (const float*)d_in[6];
    const float* b0      = (const float*)d_in[7];
    const float* g1      = (const float*)d_in[8];
    const float* b1      = (const float*)d_in[9];
    const float* w_mlp1  = (const float*)d_in[10];
    const float* b_mlp1  = (const float*)d_in[11];
    const float* w_mlp2  = (const float*)d_in[12];
    const float* b_mlp2  = (const float*)d_in[13];
    const float* w_skip  = (const float*)d_in[14];
    const float* w_dec0  = (const float*)d_in[15];
    const float* b_dec0  = (const float*)d_in[16];
    const float* w_dec1  = (const float*)d_in[17];
    float* out = (float*)d_out;

    float *Pwf,*PivDf,*Pws,*PivDs,*Tff,*Tif,*Tfs,*Tis,*Wbig;
    float *wTe0,*wTe1,*wTm1,*wTm2,*wTsk,*wTd0,*wTd1;
    float *xin,*bufA,*bufBC,*bufD,*bufE,*bufH,*G1,*Gc,*cAB,*cRaw,*stats8;
    SYMP(Pwf, g_Pw_full);  SYMP(PivDf, g_PinvD_full);
    SYMP(Pws, g_Pw_small); SYMP(PivDs, g_PinvD_small);
    SYMP(Tff, g_Tf_full);  SYMP(Tif, g_Ti_full);
    SYMP(Tfs, g_Tf_small); SYMP(Tis, g_Ti_small);
    SYMP(Wbig, g_Wbig);
    SYMP(wTe0, g_wT_enc0); SYMP(wTe1, g_wT_enc1);
    SYMP(wTm1, g_wT_mlp1); SYMP(wTm2, g_wT_mlp2); SYMP(wTsk, g_wT_skip);
    SYMP(wTd0, g_wT_dec0); SYMP(wTd1, g_wT_dec1);
    SYMP(xin, g_xin);
    SYMP(bufA, g_bufA); SYMP(bufBC, g_bufBC);
    SYMP(bufD, g_bufD); SYMP(bufE, g_bufE); SYMP(bufH, g_bufH);
    SYMP(G1, g_G1); SYMP(Gc, g_Gc); SYMP(cAB, g_cAB); SYMP(cRaw, g_cRaw);
    SYMP(stats8, g_stats8);

    float* bufB = bufBC;
    float* bufC = bufBC + (long long)PFULL*EDIM;
    const long long SC2 = (long long)PFULL*EDIM;

    dim3 t32(32, 32);

    // ---- launches 0..5: slot 5 = encoder GEMM #2 (profiled control) ----
    transpose_tiled_k<<<dim3((PFULL+31)/32, 1), t32>>>(x_in, xin, CINCH, PFULL);               // 0
    wtrans_all_k<<<dim3(128, 16), 256>>>(w_enc0, w_enc1, w_mlp1, w_mlp2, w_skip, w_dec0, w_dec1,
                                         wTe0, wTe1, wTm1, wTm2, wTsk, wTd0, wTd1);            // 1
    legtab_k<<<(LMAXD*MMAXD+255)/256, 256>>>();                                                // 2
    launch_gemm(xin,  wTe0, bufD, b_enc0, nullptr, PFULL, EDIM, CINCH, CINCH, EDIM, EDIM, 0,0,0, 1, 1); // 3
    legendre_both_k<<<((NLAT+TSM)*MMAXD+255)/256, 256>>>(Pwf, PivDf, Pws, PivDs);              // 4
    launch_gemm(bufD, wTe1, bufA, nullptr, nullptr, PFULL, EDIM, EDIM, EDIM, EDIM, EDIM, 0,0,0, 1, 0);  // 5 <- profiled

    fft_both_k<<<dim3((MMAXD*NLONF+255)/256, 2), 256>>>(Tff, Tif, Tfs, Tis);
    build_wbig2_k<<<dim3(2, EDIM, NBLK), 256>>>(w_specr, w_speci, Wbig);
    zero_k<<<(8*2*EDIM+255)/256, 256>>>(stats8, 8*2*EDIM);

    // ---- blocks ----
    struct Blk { int Tin, nlin, Tout, nlout; bool sres; };
    const Blk blks[NBLK] = {
        {NLAT, NLONF, TSM, NLONS, true},
        {TSM, NLONS, TSM, NLONS, false},
        {TSM, NLONS, TSM, NLONS, false},
        {TSM, NLONS, NLAT, NLONF, true},
    };
    float* infld[NBLK]  = {bufA, bufA, bufE, bufA};
    float* outfld[NBLK] = {bufA, bufE, bufA, bufB};

    for (int i = 0; i < NBLK; i++){
        const Blk& bk = blks[i];
        const float* Tf_in  = (bk.nlin == NLONF) ? Tff : Tfs;
        const float* Pw_in  = (bk.Tin == NLAT) ? Pwf : Pws;
        const float* PivD   = (bk.Tout == NLAT) ? PivDf : PivDs;
        const float* Ti_out = (bk.nlout == NLONF) ? Tif : Tis;
        int Pout = bk.Tout * bk.nlout;
        float invP = 1.0f/(float)Pout;
        float* in = infld[i];
        float* xout = outfld[i];
        float* st0 = stats8 + (long long)(2*i)*2*EDIM;
        float* st1 = stats8 + (long long)(2*i+1)*2*EDIM;

        // forward rFFT: G1[t][m2][ch] (batch over t)
        launch_gemm(Tf_in, in, G1, nullptr, nullptr,
                    M2, EDIM, bk.nlin, bk.nlin, EDIM, EDIM,
                    0, (long long)bk.nlin*EDIM, (long long)M2*EDIM, bk.Tin, 0);
        // Legendre analysis -> cRaw (batch over m; tri=3 skips dead l<m tiles)
        launch_gemm(Pw_in, G1, cRaw, nullptr, nullptr,
                    LMAXD, 256, bk.Tin, MMAXD*bk.Tin, M2*EDIM, MMAXD*256,
                    bk.Tin, 256, 256, MMAXD, 0,
                    nullptr, 0.f, nullptr, nullptr, 3);
        // spectral conv (batch over l; tri=2 skips m>l tiles)
        launch_gemm(cRaw, Wbig + (long long)i*LMAXD*65536, cAB, nullptr, nullptr,
                    MMAXD, 256, 256, 256, 256, 256,
                    (long long)MMAXD*256, 65536, (long long)M2*256, LMAXD, 0,
                    nullptr, 0.f, nullptr, nullptr, 2);
        int nz = bk.sres ? M2 : MMAXD;
        if (bk.sres){
            // spectral skip (K=128, tri=7 triangular CTA skip)
            launch_gemm(cRaw, wTsk + (long long)i*EDIM*EDIM, cAB + MMAXD*256, nullptr, nullptr,
                        M2, EDIM, EDIM, EDIM, EDIM, EDIM,
                        (long long)MMAXD*256, 0, (long long)M2*256, LMAXD, 0,
                        nullptr, 0.f, nullptr, nullptr, 7);
        }
        // synthesis (batch over z; tri=1 clamps K to l>=m)
        launch_gemm(PivD, cAB, Gc, nullptr, nullptr,
                    bk.Tout, 256, LMAXD, LMAXD, M2*256, M2*256,
                    (long long)bk.Tout*LMAXD, 256, 256, nz, 0,
                    nullptr, 0.f, nullptr, nullptr, 1);
        if (bk.sres){
            launch_gemm(Ti_out, Gc, bufB, nullptr, nullptr,
                        bk.nlout, EDIM, M2, M2, EDIM, EDIM,
                        0, (long long)M2*256, (long long)bk.nlout*EDIM, 2*bk.Tout, 0,
                        nullptr, 0.f, nullptr, nullptr, 4, (long long)MMAXD*256, SC2, st0);
        } else {
            launch_gemm(Ti_out, Gc, bufB, nullptr, nullptr,
                        bk.nlout, EDIM, M2, M2, EDIM, EDIM,
                        0, (long long)M2*256, (long long)bk.nlout*EDIM, bk.Tout, 0,
                        nullptr, 0.f, nullptr, nullptr, 0, 0, 0, st0);
        }

        // MLP1: norm0 apply+gelu fused into A-loads (murs from st0 per CTA)
        launch_gemm(bufB, wTm1 + (long long)i*EDIM*HID, bufH, b_mlp1 + (long long)i*HID, nullptr,
                    Pout, HID, EDIM, EDIM, HID, HID, 0,0,0, 1, 1,
                    st0, invP, g0 + (long long)i*EDIM, b0 + (long long)i*EDIM, 0);
        // MLP2 accumulates norm1 stats in its epilogue
        launch_gemm(bufH, wTm2 + (long long)i*HID*EDIM, bufB, b_mlp2 + (long long)i*EDIM, nullptr,
                    Pout, EDIM, HID, HID, EDIM, EDIM, 0,0,0, 1, 0,
                    nullptr, 0.f, nullptr, nullptr, 0, 0, 0, st1);
        if (bk.sres){
            long long tot4 = (long long)Pout*EDIM/4;
            inorm_add_k<<<(unsigned)((tot4+255)/256), 256>>>(bufB, bufC, xout, st1, invP,
                    g1 + (long long)i*EDIM, b1 + (long long)i*EDIM, tot4);
        } else {
            launch_gemm(in, wTsk + (long long)i*EDIM*EDIM, xout, nullptr, bufB,
                        Pout, EDIM, EDIM, EDIM, EDIM, EDIM, 0,0,0, 1, 3,
                        st1, invP, g1 + (long long)i*EDIM, b1 + (long long)i*EDIM, 0);
        }
    }

    // ---- decoder (R12 form: split K = 128 + 26, fused gelu epilogue) ----
    launch_gemm(bufB, wTd0, bufD, nullptr, nullptr,
                PFULL, EDIM, EDIM, EDIM, EDIM, EDIM, 0,0,0, 1, 0);
    launch_gemm(xin, wTd0 + EDIM*EDIM, bufA, b_dec0, bufD,
                PFULL, EDIM, CINCH, CINCH, EDIM, EDIM, 0,0,0, 1, 2);
    launch_gemm(bufA, wTd1, bufC, nullptr, nullptr,
                PFULL, COUTCH, EDIM, EDIM, COUTCH, COUTCH, 0,0,0, 1, 0);
    transpose_tiled_k<<<dim3(1, (PFULL+31)/32), t32>>>(bufC, out, PFULL, COUTCH);
}

// round 16
// speedup vs baseline: 1.0695x; 1.0695x over previous
#include <cuda_runtime.h>
#include <math.h>

#ifndef M_PI
#define M_PI 3.14159265358979323846
#endif

// ---------------- dims ----------------
#define EDIM 128
#define HID 256
#define CINCH 26
#define COUTCH 26
#define NLAT 361
#define NLONF 720
#define TSM 90
#define NLONS 180
#define LMAXD 90
#define MMAXD 91
#define M2 182            // 2*MMAX (re,im rows)
#define PFULL (NLAT*NLONF)   // 259920
#define PSMALL (TSM*NLONS)   // 16200
#define NBLK 4

typedef unsigned long long u64;

// ---------------- device scratch ----------------
__device__ float g_Pw_full[LMAXD*MMAXD*NLAT];
__device__ float g_PinvD_full[M2*NLAT*LMAXD];     // duplicated: [182][t][l]
__device__ float g_Pw_small[LMAXD*MMAXD*TSM];
__device__ float g_PinvD_small[M2*TSM*LMAXD];
__device__ float g_Tf_full[M2*NLONF];
__device__ float g_Ti_full[NLONF*M2];
__device__ float g_Tf_small[M2*NLONS];
__device__ float g_Ti_small[NLONS*M2];
__device__ float g_Wbig[(long long)NBLK*LMAXD*65536];
__device__ float g_wT_enc0[CINCH*EDIM];
__device__ float g_wT_enc1[EDIM*EDIM];
__device__ float g_wT_mlp1[NBLK*EDIM*HID];
__device__ float g_wT_mlp2[NBLK*HID*EDIM];
__device__ float g_wT_skip[NBLK*EDIM*EDIM];
__device__ float g_wT_dec0[(EDIM+CINCH)*EDIM];
__device__ float g_wT_dec1[EDIM*COUTCH];
__device__ float g_xin[PFULL*CINCH];
__device__ float g_bufA[PFULL*EDIM];
__device__ float g_bufBC[2ll*PFULL*EDIM];         // bufB = first half, bufC = second half
__device__ float g_bufD[PFULL*EDIM];
__device__ float g_bufE[PSMALL*EDIM];
__device__ float g_bufH[PFULL*HID];
__device__ float g_G1[NLAT*M2*EDIM];              // fwd-rFFT output [t][m2][128]
__device__ float g_Gc[NLAT*M2*256];               // combined synthesis out [t][182][256]
__device__ float g_cAB[LMAXD*M2*256];             // [l][182][256]: z<91 spec, z>=91 res(skip)
__device__ float g_cRaw[LMAXD*MMAXD*256];         // raw analysis coeffs [l][91][256]
__device__ float g_stats[2*EDIM];                 // zero-init; every finalize self-resets
__device__ float g_murs[2*EDIM];
// legendre recurrence tables
__device__ double2 g_ab[LMAXD*MMAXD];
__device__ double g_pdiag[MMAXD];
__device__ double g_em[MMAXD];

__device__ __forceinline__ float gelu_f(float x){
    return 0.5f*x*(1.0f+erff(x*0.7071067811865475f));
}

// ---------------- setup kernels ----------------
__global__ void legtab_k(){
    int gid = blockIdx.x*blockDim.x + threadIdx.x;
    if (gid < LMAXD*MMAXD){
        int m = gid % MMAXD, l = gid / MMAXD;
        double2 ab = {0.0, 0.0};
        if (m < LMAXD && l >= m+2){
            double dl = (double)l, dm = (double)m;
            ab.x = sqrt((4.0*dl*dl-1.0)/(dl*dl-dm*dm));
            ab.y = sqrt(((dl-1.0)*(dl-1.0)-dm*dm)/(4.0*(dl-1.0)*(dl-1.0)-1.0));
        }
        g_ab[gid] = ab;
    }
    if (gid < MMAXD){
        double p = 1.0;
        for (int mm = 1; mm <= gid; mm++)
            p *= sqrt((2.0*mm+1.0)/(2.0*mm));
        g_pdiag[gid] = p;
        g_em[gid] = sqrt(2.0*gid+3.0);
    }
}

__device__ __forceinline__ void legendre_body(float* __restrict__ Pw, float* __restrict__ PinvD,
                                              int T, int gid){
    int t = gid % T, m = gid / T;
    long long d0 = ((long long)m*T + t)*LMAXD;
    long long d1 = ((long long)(MMAXD+m)*T + t)*LMAXD;
    if (m >= LMAXD){
        for (int l = 0; l < LMAXD; l++){
            Pw[((long long)l*MMAXD + m)*T + t] = 0.f;
            PinvD[d0 + l] = 0.f;
            PinvD[d1 + l] = 0.f;
        }
        return;
    }
    double theta = M_PI*((double)t + 0.5)/(double)T;
    double ct = cos(theta), st = sin(theta);
    double w = (M_PI/(double)T)*st;
    double diag = sqrt(1.0/(4.0*M_PI)) * g_pdiag[m] * pow(st, (double)m);
    double em = g_em[m];
    double pl1 = 0.0, pl2 = 0.0;
    for (int l = 0; l < LMAXD; l++){
        double v;
        if (l < m) v = 0.0;
        else if (l == m) v = diag;
        else if (l == m+1) v = em*ct*diag;
        else {
            double2 ab = g_ab[l*MMAXD + m];
            v = ab.x*(ct*pl1 - ab.y*pl2);
        }
        pl2 = pl1; pl1 = v;
        Pw[((long long)l*MMAXD + m)*T + t] = (float)(v*w);
        float fv = (float)v;
        PinvD[d0 + l] = fv;
        PinvD[d1 + l] = fv;
    }
}

__global__ void legendre_both_k(float* Pwf, float* PinvDf, float* Pws, float* PinvDs){
    int gid = blockIdx.x*blockDim.x + threadIdx.x;
    const int totf = NLAT*MMAXD;
    if (gid < totf) legendre_body(Pwf, PinvDf, NLAT, gid);
    else if (gid < totf + TSM*MMAXD) legendre_body(Pws, PinvDs, TSM, gid - totf);
}

__global__ void fft_both_k(float* Tff, float* Tif, float* Tfs, float* Tis){
    int n = (blockIdx.y == 0) ? NLONF : NLONS;
    float* Tf = (blockIdx.y == 0) ? Tff : Tfs;
    float* Ti = (blockIdx.y == 0) ? Tif : Tis;
    int idx = blockIdx.x*blockDim.x + threadIdx.x;
    if (idx >= MMAXD*n) return;
    int m = idx / n, j = idx % n;
    double ang = (2.0*M_PI*(double)m*(double)j)/(double)n;
    double s, c;
    sincos(ang, &s, &c);
    double sc = 2.0*M_PI/(double)n;
    Tf[(2*m)*n + j]   = (float)(c*sc);
    Tf[(2*m+1)*n + j] = (float)(-s*sc);
    bool nyq = (2*m == n);
    double am = (m == 0 || nyq) ? 1.0 : 2.0;
    Ti[(long long)j*M2 + 2*m]   = (float)(am*c);
    Ti[(long long)j*M2 + 2*m+1] = (m == 0 || nyq) ? 0.0f : (float)(-2.0*s);
}

__global__ void wtrans_all_k(const float* w_enc0, const float* w_enc1,
                             const float* w_mlp1, const float* w_mlp2, const float* w_skip,
                             const float* w_dec0, const float* w_dec1,
                             float* wTe0, float* wTe1, float* wTm1, float* wTm2,
                             float* wTsk, float* wTd0, float* wTd1){
    int seg = blockIdx.y;
    const float* src; float* dst; int R, C;
    if (seg == 0){ src = w_enc0; dst = wTe0; R = EDIM; C = CINCH; }
    else if (seg == 1){ src = w_enc1; dst = wTe1; R = EDIM; C = EDIM; }
    else if (seg < 6){ int i = seg-2; src = w_mlp1 + (long long)i*HID*EDIM; dst = wTm1 + (long long)i*EDIM*HID; R = HID; C = EDIM; }
    else if (seg < 10){ int i = seg-6; src = w_mlp2 + (long long)i*EDIM*HID; dst = wTm2 + (long long)i*HID*EDIM; R = EDIM; C = HID; }
    else if (seg < 14){ int i = seg-10; src = w_skip + (long long)i*EDIM*EDIM; dst = wTsk + (long long)i*EDIM*EDIM; R = EDIM; C = EDIM; }
    else if (seg == 14){ src = w_dec0; dst = wTd0; R = EDIM; C = EDIM+CINCH; }
    else { src = w_dec1; dst = wTd1; R = COUTCH; C = EDIM; }
    int tot = R*C;
    for (int idx = blockIdx.x*blockDim.x + threadIdx.x; idx < tot; idx += gridDim.x*blockDim.x){
        int c = idx % C, r = idx / C;
        dst[(long long)c*R + r] = src[idx];
    }
}

__global__ void transpose_tiled_k(const float* __restrict__ in, float* __restrict__ out,
                                  int R, int C){
    __shared__ float tile[32][33];
    int c0 = blockIdx.x*32, r0 = blockIdx.y*32;
    int tx = threadIdx.x, ty = threadIdx.y;
    int r = r0 + ty, c = c0 + tx;
    if (r < R && c < C) tile[ty][tx] = in[(long long)r*C + c];
    __syncthreads();
    int r2 = r0 + tx, c2 = c0 + ty;
    if (r2 < R && c2 < C) out[(long long)c2*R + r2] = tile[tx][ty];
}

__global__ void build_wbig2_k(const float* __restrict__ wr, const float* __restrict__ wi,
                              float* __restrict__ W){
    __shared__ float sr[64*90];
    __shared__ float si[64*90];
    int oh = blockIdx.x;
    int i  = blockIdx.y;
    int b  = blockIdx.z;
    int tid = threadIdx.x;
    for (int j = tid; j < 64*90; j += 256){
        int ol = j / 90, l = j % 90;
        int o = oh*64 + ol;
        long long src = (((long long)b*EDIM + o)*EDIM + i)*LMAXD + l;
        sr[j] = wr[src];
        si[j] = wi[src];
    }
    __syncthreads();
    for (int j = tid; j < 64*90; j += 256){
        int l = j / 64, ol = j % 64;
        int o = oh*64 + ol;
        float vr = sr[ol*90 + l], vi = si[ol*90 + l];
        float* M = W + ((long long)b*LMAXD + l)*65536;
        M[(long long)i*256 + o]             = vr;
        M[(long long)i*256 + 128 + o]       = vi;
        M[(long long)(128+i)*256 + o]       = -vi;
        M[(long long)(128+i)*256 + 128 + o] = vr;
    }
}

__global__ void zero_k(float* p, int n){
    int i = blockIdx.x*blockDim.x + threadIdx.x;
    if (i < n) p[i] = 0.0f;
}

// ---------------- instance norm finalize (stats accumulated in GEMM epilogues) ----------------
__global__ void inorm_fin2_k(float* __restrict__ stats, float* __restrict__ murs, float invP){
    int ch = threadIdx.x;
    float mu = stats[ch]*invP;
    float var = stats[EDIM+ch]*invP - mu*mu;
    murs[ch] = mu;
    murs[EDIM+ch] = rsqrtf(var + 1e-6f);
    stats[ch] = 0.f;
    stats[EDIM+ch] = 0.f;
}

// y = inorm(b) + c
__global__ void inorm_add_k(const float* __restrict__ b, const float* __restrict__ c,
                            float* __restrict__ y, const float* __restrict__ murs,
                            const float* __restrict__ g, const float* __restrict__ bb,
                            long long total4){
    long long i = (long long)blockIdx.x*blockDim.x + threadIdx.x;
    if (i >= total4) return;
    int ch = (int)((i & 31) << 2);
    float4 vb = ((const float4*)b)[i];
    float4 vc = ((const float4*)c)[i];
    float4 o;
    o.x = (vb.x - murs[ch  ])*murs[EDIM+ch  ]*g[ch  ] + bb[ch  ] + vc.x;
    o.y = (vb.y - murs[ch+1])*murs[EDIM+ch+1]*g[ch+1] + bb[ch+1] + vc.y;
    o.z = (vb.z - murs[ch+2])*murs[EDIM+ch+2]*g[ch+2] + bb[ch+2] + vc.z;
    o.w = (vb.w - murs[ch+3])*murs[EDIM+ch+3]*g[ch+3] + bb[ch+3] + vc.w;
    ((float4*)y)[i] = o;
}

// ---------------- generic batched GEMM (FFMA2 inner loop; hot path == R12) ----------------
// act: 0 none; 1 gelu(acc+bias) then +add; 2 gelu(acc+bias+add); 3 acc + inorm(addp)
// nrm != null && act != 3: A loads -> gelu((a-mu[k])*rs[k]*ng[k]+nb[k])
// tri: 0 none; 1 per-batch K-clamp k_start=z%91; 2 skip CTA if m0 > z;
//      3 skip CTA if m0+TBM <= z; 4 dual out: r=z&1, z>>=1, B+=r*sB2, C+=r*sC2;
//      7 skip CTA if (m0>>1) > z (spectral-skip triangular; entry-only)
// sstat: accumulate per-channel sum/sumsq of written C (requires N==128 grid.x==1)
#define BN 128
#define BKK 16

template<int TBM>
__global__ __launch_bounds__(512, 2)
void gemm_k(const float* __restrict__ A, const float* __restrict__ B,
            float* __restrict__ C,
            const float* __restrict__ bias, const float* __restrict__ addp,
            int M, int N, int K, int lda, int ldb, int ldc,
            long long sA, long long sB, long long sC, int act,
            const float* __restrict__ nrm, const float* __restrict__ ng,
            const float* __restrict__ nb, int tri, long long sB2, long long sC2,
            float* __restrict__ sstat){
    constexpr int MR = TBM/16;
    constexpr int ALD = (TBM == 128) ? 4 : 2;
    __shared__ float As[2][BKK][TBM+4];
    __shared__ float Bs[2][BKK][BN];

    long long z = blockIdx.z;
    int m0 = blockIdx.y*TBM, n0 = blockIdx.x*BN;

    int rpair = 0;
    if (tri == 4){ rpair = (int)(z & 1); z >>= 1; if (rpair) sstat = nullptr; }
    else if (tri == 2){ if (m0 > (int)z) return; }
    else if (tri == 3){ if (m0 + TBM <= (int)z) return; }
    else if (tri == 7){ if ((m0 >> 1) > (int)z) return; }

    A += z*sA; B += z*sB + (long long)rpair*sB2; C += z*sC + (long long)rpair*sC2;
    if (addp) addp += z*sC;
    if (tri == 1){
        int mm = (int)(z % MMAXD);
        A += mm;
        B += (long long)mm*ldb;
        K -= mm;
    }
    int tid = threadIdx.x;

    int a_m = (TBM == 128) ? (tid >> 2) : (tid >> 3);
    int a_k = (TBM == 128) ? ((tid & 3)*ALD) : ((tid & 7)*ALD);
    int b_k = tid >> 5;
    int b_n = (tid & 31) * 4;

    int ty = tid >> 5;
    int tx = tid & 31;

    const bool doNA = (nrm != nullptr) && (act != 3);

    bool am_ok = (m0 + a_m) < M;
    const float* Ap = A + (long long)(am_ok ? (m0 + a_m) : 0)*lda + a_k;
    const float* Bp = B + (long long)b_k*ldb + n0 + b_n;
    bool bn_ok[4];
    #pragma unroll
    for (int s = 0; s < 4; s++) bn_ok[s] = (n0 + b_n + s) < N;

    int ktiles = (K + BKK - 1)/BKK;

    u64 acc2[MR/2][4];
    #pragma unroll
    for (int rq = 0; rq < MR/2; rq++)
        #pragma unroll
        for (int c = 0; c < 4; c++)
            acc2[rq][c] = 0ull;
    float ra[ALD], rb[4];

    {
        #pragma unroll
        for (int s = 0; s < ALD; s++){
            bool ok = am_ok && (a_k+s) < K;
            float a = ok ? Ap[s] : 0.f;
            if (doNA && ok){
                int ch = a_k + s;
                a = gelu_f((a - nrm[ch])*nrm[EDIM+ch]*ng[ch] + nb[ch]);
            }
            As[0][a_k+s][a_m] = a;
        }
        #pragma unroll
        for (int s = 0; s < 4; s++)
            Bs[0][b_k][b_n+s] = (b_k < K && bn_ok[s]) ? Bp[s] : 0.f;
    }
    __syncthreads();
    Ap += BKK; Bp += (long long)BKK*ldb;

    int buf = 0;
    for (int it = 0; it < ktiles; it++){
        bool haveNext = (it + 1 < ktiles);
        if (haveNext){
            int kbase = (it + 1)*BKK;
            if (kbase + BKK <= K){
                #pragma unroll
                for (int s = 0; s < ALD; s++){
                    ra[s] = am_ok ? Ap[s] : 0.f;
                    if (doNA && am_ok){
                        int ch = kbase + a_k + s;
                        ra[s] = gelu_f((ra[s] - nrm[ch])*nrm[EDIM+ch]*ng[ch] + nb[ch]);
                    }
                }
                #pragma unroll
                for (int s = 0; s < 4; s++) rb[s] = bn_ok[s] ? Bp[s] : 0.f;
            } else {
                #pragma unroll
                for (int s = 0; s < ALD; s++){
                    bool ok = am_ok && (kbase + a_k + s) < K;
                    ra[s] = ok ? Ap[s] : 0.f;
                    if (doNA && ok){
                        int ch = kbase + a_k + s;
                        ra[s] = gelu_f((ra[s] - nrm[ch])*nrm[EDIM+ch]*ng[ch] + nb[ch]);
                    }
                }
                #pragma unroll
                for (int s = 0; s < 4; s++)
                    rb[s] = ((kbase + b_k) < K && bn_ok[s]) ? Bp[s] : 0.f;
            }
            Ap += BKK; Bp += (long long)BKK*ldb;
        }
        #pragma unroll
        for (int k = 0; k < BKK; k++){
            float4 b0 = *(const float4*)&Bs[buf][k][tx*4];
            u64 bb[4];
            asm("mov.b64 %0, {%1,%1};" : "=l"(bb[0]) : "r"(__float_as_uint(b0.x)));
            asm("mov.b64 %0, {%1,%1};" : "=l"(bb[1]) : "r"(__float_as_uint(b0.y)));
            asm("mov.b64 %0, {%1,%1};" : "=l"(bb[2]) : "r"(__float_as_uint(b0.z)));
            asm("mov.b64 %0, {%1,%1};" : "=l"(bb[3]) : "r"(__float_as_uint(b0.w)));
            #pragma unroll
            for (int rq = 0; rq < MR/2; rq++){
                u64 ap = *(const u64*)&As[buf][k][ty*MR + rq*2];
                #pragma unroll
                for (int c = 0; c < 4; c++)
                    asm("fma.rn.f32x2 %0, %1, %2, %0;"
                        : "+l"(acc2[rq][c]) : "l"(ap), "l"(bb[c]));
            }
        }
        if (haveNext){
            int nbuf = buf ^ 1;
            #pragma unroll
            for (int s = 0; s < ALD; s++)
                As[nbuf][a_k+s][a_m] = ra[s];
            #pragma unroll
            for (int s = 0; s < 4; s++)
                Bs[nbuf][b_k][b_n+s] = rb[s];
        }
        __syncthreads();
        buf ^= 1;
    }

    float cs[4] = {0.f,0.f,0.f,0.f};
    float cq[4] = {0.f,0.f,0.f,0.f};
    #pragma unroll
    for (int rq = 0; rq < MR/2; rq++){
        #pragma unroll
        for (int c = 0; c < 4; c++){
            unsigned lo, hi;
            asm("mov.b64 {%0,%1}, %2;" : "=r"(lo), "=r"(hi) : "l"(acc2[rq][c]));
            float v0 = __uint_as_float(lo);
            float v1 = __uint_as_float(hi);
            #pragma unroll
            for (int half = 0; half < 2; half++){
                float v = half ? v1 : v0;
                int m = m0 + ty*MR + rq*2 + half;
                int n = n0 + tx*4 + c;
                if (m >= M || n >= N) continue;
                if (bias) v += bias[n];
                if (act == 2){
                    v += addp[(long long)m*ldc + n];
                    v = gelu_f(v);
                } else if (act == 3){
                    float ad = addp[(long long)m*ldc + n];
                    v += (ad - nrm[n])*nrm[EDIM+n]*ng[n] + nb[n];
                } else {
                    if (act == 1) v = gelu_f(v);
                    if (addp) v += addp[(long long)m*ldc + n];
                }
                C[(long long)m*ldc + n] = v;
                if (sstat){ cs[c] += v; cq[c] += v*v; }
            }
        }
    }
    if (sstat){
        __syncthreads();
        float* rs = &As[0][0][0];
        float* rq2 = &Bs[0][0][0];
        int base = ty*128 + tx*4;
        #pragma unroll
        for (int c = 0; c < 4; c++){ rs[base+c] = cs[c]; rq2[base+c] = cq[c]; }
        __syncthreads();
        if (tid < 128){
            float s = 0.f, q = 0.f;
            #pragma unroll
            for (int t = 0; t < 16; t++){ s += rs[t*128 + tid]; q += rq2[t*128 + tid]; }
            atomicAdd(&sstat[tid], s);
            atomicAdd(&sstat[EDIM + tid], q);
        }
    }
}

// ---------------- host helpers ----------------
static void launch_gemm(const float* A, const float* B, float* C,
                        const float* bias, const float* addp,
                        int M, int N, int K, int lda, int ldb, int ldc,
                        long long sA, long long sB, long long sC, int batch, int act,
                        const float* nrm = nullptr, const float* ng = nullptr,
                        const float* nb = nullptr, int tri = 0,
                        long long sB2 = 0, long long sC2 = 0,
                        float* sstat = nullptr){
    if (M <= 192){
        dim3 grid((N+BN-1)/BN, (M+63)/64, batch);
        gemm_k<64><<<grid, 512>>>(A, B, C, bias, addp, M, N, K, lda, ldb, ldc, sA, sB, sC, act, nrm, ng, nb, tri, sB2, sC2, sstat);
    } else {
        dim3 grid((N+BN-1)/BN, (M+127)/128, batch);
        gemm_k<128><<<grid, 512>>>(A, B, C, bias, addp, M, N, K, lda, ldb, ldc, sA, sB, sC, act, nrm, ng, nb, tri, sB2, sC2, sstat);
    }
}

#define SYMP(var, sym) do { void* _t = nullptr; cudaGetSymbolAddress(&_t, sym); var = (float*)_t; } while(0)

extern "C" void kernel_launch(void* const* d_in, const int* in_sizes, int n_in,
                              void* d_out, int out_size){
    const float* x_in    = (const float*)d_in[0];
    const float* w_enc0  = (const float*)d_in[1];
    const float* b_enc0  = (const float*)d_in[2];
    const float* w_enc1  = (const float*)d_in[3];
    const float* w_specr = (const float*)d_in[4];
    const float* w_speci = (const float*)d_in[5];
    const float* g0      = (const float*)d_in[6];
    const float* b0      = (const float*)d_in[7];
    const float* g1      = (const float*)d_in[8];
    const float* b1      = (const float*)d_in[9];
    const float* w_mlp1  = (const float*)d_in[10];
    const float* b_mlp1  = (const float*)d_in[11];
    const float* w_mlp2  = (const float*)d_in[12];
    const float* b_mlp2  = (const float*)d_in[13];
    const float* w_skip  = (const float*)d_in[14];
    const float* w_dec0  = (const float*)d_in[15];
    const float* b_dec0  = (const float*)d_in[16];
    const float* w_dec1  = (const float*)d_in[17];
    float* out = (float*)d_out;

    float *Pwf,*PivDf,*Pws,*PivDs,*Tff,*Tif,*Tfs,*Tis,*Wbig;
    float *wTe0,*wTe1,*wTm1,*wTm2,*wTsk,*wTd0,*wTd1;
    float *xin,*bufA,*bufBC,*bufD,*bufE,*bufH,*G1,*Gc,*cAB,*cRaw,*stats,*murs;
    SYMP(Pwf, g_Pw_full);  SYMP(PivDf, g_PinvD_full);
    SYMP(Pws, g_Pw_small); SYMP(PivDs, g_PinvD_small);
    SYMP(Tff, g_Tf_full);  SYMP(Tif, g_Ti_full);
    SYMP(Tfs, g_Tf_small); SYMP(Tis, g_Ti_small);
    SYMP(Wbig, g_Wbig);
    SYMP(wTe0, g_wT_enc0); SYMP(wTe1, g_wT_enc1);
    SYMP(wTm1, g_wT_mlp1); SYMP(wTm2, g_wT_mlp2); SYMP(wTsk, g_wT_skip);
    SYMP(wTd0, g_wT_dec0); SYMP(wTd1, g_wT_dec1);
    SYMP(xin, g_xin);
    SYMP(bufA, g_bufA); SYMP(bufBC, g_bufBC);
    SYMP(bufD, g_bufD); SYMP(bufE, g_bufE); SYMP(bufH, g_bufH);
    SYMP(G1, g_G1); SYMP(Gc, g_Gc); SYMP(cAB, g_cAB); SYMP(cRaw, g_cRaw);
    SYMP(stats, g_stats); SYMP(murs, g_murs);

    float* bufB = bufBC;
    float* bufC = bufBC + (long long)PFULL*EDIM;
    const long long SC2 = (long long)PFULL*EDIM;

    dim3 t32(32, 32);

    // ---- launches 0..5: slot 5 = encoder GEMM #2 (profiled control) ----
    transpose_tiled_k<<<dim3((PFULL+31)/32, 1), t32>>>(x_in, xin, CINCH, PFULL);               // 0
    wtrans_all_k<<<dim3(128, 16), 256>>>(w_enc0, w_enc1, w_mlp1, w_mlp2, w_skip, w_dec0, w_dec1,
                                         wTe0, wTe1, wTm1, wTm2, wTsk, wTd0, wTd1);            // 1
    legtab_k<<<(LMAXD*MMAXD+255)/256, 256>>>();                                                // 2
    launch_gemm(xin,  wTe0, bufD, b_enc0, nullptr, PFULL, EDIM, CINCH, CINCH, EDIM, EDIM, 0,0,0, 1, 1); // 3
    legendre_both_k<<<((NLAT+TSM)*MMAXD+255)/256, 256>>>(Pwf, PivDf, Pws, PivDs);              // 4
    launch_gemm(bufD, wTe1, bufA, nullptr, nullptr, PFULL, EDIM, EDIM, EDIM, EDIM, EDIM, 0,0,0, 1, 0);  // 5 <- profiled

    fft_both_k<<<dim3((MMAXD*NLONF+255)/256, 2), 256>>>(Tff, Tif, Tfs, Tis);
    build_wbig2_k<<<dim3(2, EDIM, NBLK), 256>>>(w_specr, w_speci, Wbig);
    zero_k<<<1, 256>>>(stats, 2*EDIM);

    // ---- blocks ----
    struct Blk { int Tin, nlin, Tout, nlout; bool sres; };
    const Blk blks[NBLK] = {
        {NLAT, NLONF, TSM, NLONS, true},
        {TSM, NLONS, TSM, NLONS, false},
        {TSM, NLONS, TSM, NLONS, false},
        {TSM, NLONS, NLAT, NLONF, true},
    };
    float* infld[NBLK]  = {bufA, bufA, bufE, bufA};
    float* outfld[NBLK] = {bufA, bufE, bufA, bufB};

    for (int i = 0; i < NBLK; i++){
        const Blk& bk = blks[i];
        const float* Tf_in  = (bk.nlin == NLONF) ? Tff : Tfs;
        const float* Pw_in  = (bk.Tin == NLAT) ? Pwf : Pws;
        const float* PivD   = (bk.Tout == NLAT) ? PivDf : PivDs;
        const float* Ti_out = (bk.nlout == NLONF) ? Tif : Tis;
        int Pout = bk.Tout * bk.nlout;
        float* in = infld[i];
        float* xout = outfld[i];

        // forward rFFT: G1[t][m2][ch] (batch over t)
        launch_gemm(Tf_in, in, G1, nullptr, nullptr,
                    M2, EDIM, bk.nlin, bk.nlin, EDIM, EDIM,
                    0, (long long)bk.nlin*EDIM, (long long)M2*EDIM, bk.Tin, 0);
        // Legendre analysis -> cRaw (batch over m; tri=3 skips dead l<m tiles)
        launch_gemm(Pw_in, G1, cRaw, nullptr, nullptr,
                    LMAXD, 256, bk.Tin, MMAXD*bk.Tin, M2*EDIM, MMAXD*256,
                    bk.Tin, 256, 256, MMAXD, 0,
                    nullptr, nullptr, nullptr, 3);
        // spectral conv (batch over l; tri=2 skips m>l tiles)
        launch_gemm(cRaw, Wbig + (long long)i*LMAXD*65536, cAB, nullptr, nullptr,
                    MMAXD, 256, 256, 256, 256, 256,
                    (long long)MMAXD*256, 65536, (long long)M2*256, LMAXD, 0,
                    nullptr, nullptr, nullptr, 2);
        int nz = bk.sres ? M2 : MMAXD;
        if (bk.sres){
            // spectral skip (K=128, tri=7 triangular CTA skip on dead l<m rows)
            launch_gemm(cRaw, wTsk + (long long)i*EDIM*EDIM, cAB + MMAXD*256, nullptr, nullptr,
                        M2, EDIM, EDIM, EDIM, EDIM, EDIM,
                        (long long)MMAXD*256, 0, (long long)M2*256, LMAXD, 0,
                        nullptr, nullptr, nullptr, 7);
        }
        // synthesis (batch over z; tri=1 clamps K to l>=m)
        launch_gemm(PivD, cAB, Gc, nullptr, nullptr,
                    bk.Tout, 256, LMAXD, LMAXD, M2*256, M2*256,
                    (long long)bk.Tout*LMAXD, 256, 256, nz, 0,
                    nullptr, nullptr, nullptr, 1);
        if (bk.sres){
            launch_gemm(Ti_out, Gc, bufB, nullptr, nullptr,
                        bk.nlout, EDIM, M2, M2, EDIM, EDIM,
                        0, (long long)M2*256, (long long)bk.nlout*EDIM, 2*bk.Tout, 0,
                        nullptr, nullptr, nullptr, 4, (long long)MMAXD*256, SC2, stats);
        } else {
            launch_gemm(Ti_out, Gc, bufB, nullptr, nullptr,
                        bk.nlout, EDIM, M2, M2, EDIM, EDIM,
                        0, (long long)M2*256, (long long)bk.nlout*EDIM, bk.Tout, 0,
                        nullptr, nullptr, nullptr, 0, 0, 0, stats);
        }

        // norm0 finalize; apply+gelu fused into MLP1 A-loads
        inorm_fin2_k<<<1, EDIM>>>(stats, murs, 1.0f/(float)Pout);
        launch_gemm(bufB, wTm1 + (long long)i*EDIM*HID, bufH, b_mlp1 + (long long)i*HID, nullptr,
                    Pout, HID, EDIM, EDIM, HID, HID, 0,0,0, 1, 1,
                    murs, g0 + (long long)i*EDIM, b0 + (long long)i*EDIM, 0);
        // MLP2 accumulates norm1 stats in its epilogue
        launch_gemm(bufH, wTm2 + (long long)i*HID*EDIM, bufB, b_mlp2 + (long long)i*EDIM, nullptr,
                    Pout, EDIM, HID, HID, EDIM, EDIM, 0,0,0, 1, 0,
                    nullptr, nullptr, nullptr, 0, 0, 0, stats);
        inorm_fin2_k<<<1, EDIM>>>(stats, murs, 1.0f/(float)Pout);
        if (bk.sres){
            long long tot4 = (long long)Pout*EDIM/4;
            inorm_add_k<<<(unsigned)((tot4+255)/256), 256>>>(bufB, bufC, xout, murs,
                    g1 + (long long)i*EDIM, b1 + (long long)i*EDIM, tot4);
        } else {
            launch_gemm(in, wTsk + (long long)i*EDIM*EDIM, xout, nullptr, bufB,
                        Pout, EDIM, EDIM, EDIM, EDIM, EDIM, 0,0,0, 1, 3,
                        murs, g1 + (long long)i*EDIM, b1 + (long long)i*EDIM, 0);
        }
    }

    // ---- decoder (R12 form: split K = 128 + 26, fused gelu epilogue) ----
    launch_gemm(bufB, wTd0, bufD, nullptr, nullptr,
                PFULL, EDIM, EDIM, EDIM, EDIM, EDIM, 0,0,0, 1, 0);
    launch_gemm(xin, wTd0 + EDIM*EDIM, bufA, b_dec0, bufD,
                PFULL, EDIM, CINCH, CINCH, EDIM, EDIM, 0,0,0, 1, 2);
    launch_gemm(bufA, wTd1, bufC, nullptr, nullptr,
                PFULL, COUTCH, EDIM, EDIM, COUTCH, COUTCH, 0,0,0, 1, 0);
    transpose_tiled_k<<<dim3(1, (PFULL+31)/32), t32>>>(bufC, out, PFULL, COUTCH);
}